// round 3
// baseline (speedup 1.0000x reference)
#include <cuda_runtime.h>
#include <cstdint>

// Problem shapes (fixed for this dataset)
#define VN   1000000
#define VDN  256
#define HIDN 128
#define NH   16
#define GDN  256
#define GN   50000

#define TM   128      // nodes per tile
#define KC   32       // K-chunk for GEMM1
#define ES_LD 36      // 32 + 4 pad
#define BS_LD 132     // 128 + 4 pad
#define HS_LD 132
#define W2_LD 20
#define WC_LD 260     // 256 + 4 pad

// Scratch (device globals: no allocations allowed)
__device__ float g_scores[(size_t)VN * NH];   // scores, then softmax weights (in-place)
__device__ int   g_gstart[GN + 1];            // gstart[g] = first node index with seg >= g

extern __shared__ float smem[];

// ---------------------------------------------------------------------------
// helpers
// ---------------------------------------------------------------------------
__device__ __forceinline__ float tf32r(float x) {
    uint32_t r;
    asm("cvt.rna.tf32.f32 %0, %1;" : "=r"(r) : "f"(x));
    return __uint_as_float(r);
}

__device__ __forceinline__ void mma_tf32(float c[4], const uint32_t a[4], const uint32_t b[2]) {
    asm volatile(
        "mma.sync.aligned.m16n8k8.row.col.f32.tf32.tf32.f32 "
        "{%0,%1,%2,%3}, {%4,%5,%6,%7}, {%8,%9}, {%0,%1,%2,%3};\n"
        : "+f"(c[0]), "+f"(c[1]), "+f"(c[2]), "+f"(c[3])
        : "r"(a[0]), "r"(a[1]), "r"(a[2]), "r"(a[3]), "r"(b[0]), "r"(b[1]));
}

// ---------------------------------------------------------------------------
// K0a: zero output (float4, wide grid)
// ---------------------------------------------------------------------------
__global__ void zero_kernel(float4* __restrict__ out, int n4) {
    const float4 z = make_float4(0.f, 0.f, 0.f, 0.f);
    for (int i = blockIdx.x * blockDim.x + threadIdx.x; i < n4; i += gridDim.x * blockDim.x)
        out[i] = z;
}

// ---------------------------------------------------------------------------
// K0b: segment offsets (seg is sorted ascending)
// ---------------------------------------------------------------------------
__global__ void gstart_kernel(const int* __restrict__ seg) {
    int v = blockIdx.x * blockDim.x + threadIdx.x;
    if (v >= VN) return;
    int s  = seg[v];
    int sp = (v == 0) ? -1 : seg[v - 1];
    for (int g = sp + 1; g <= s; g++) g_gstart[g] = v;
    if (v == VN - 1)
        for (int g = s + 1; g <= GN; g++) g_gstart[g] = VN;
}

// ---------------------------------------------------------------------------
// shared tile loaders (float4 vectorized)
// ---------------------------------------------------------------------------
// E chunk [128][32] -> Es (tf32-rounded), rows >= rowsValid zero-filled
__device__ __forceinline__ void load_E_chunk(float* Es, const float* __restrict__ E,
                                             int node0, int rowsValid, int kc, int tid) {
    #pragma unroll
    for (int i = 0; i < 4; i++) {               // 1024 float4 total
        int idx = tid + i * 256;
        int r = idx >> 3, c4 = idx & 7;         // row, float4-col
        float4 v = make_float4(0.f, 0.f, 0.f, 0.f);
        if (r < rowsValid)
            v = reinterpret_cast<const float4*>(E)[(size_t)(node0 + r) * (VDN / 4) + kc * 8 + c4];
        float* dst = Es + r * ES_LD + c4 * 4;
        dst[0] = tf32r(v.x); dst[1] = tf32r(v.y); dst[2] = tf32r(v.z); dst[3] = tf32r(v.w);
    }
}

// W1 chunk [32][128] -> Bs (tf32-rounded)
__device__ __forceinline__ void load_W1_chunk(float* Bs, const float* __restrict__ W1,
                                              int kc, int tid) {
    #pragma unroll
    for (int i = 0; i < 4; i++) {               // 1024 float4 total
        int idx = tid + i * 256;
        int k = idx >> 5, n4 = idx & 31;
        float4 v = reinterpret_cast<const float4*>(W1)[(size_t)(kc * KC + k) * (HIDN / 4) + n4];
        float* dst = Bs + k * BS_LD + n4 * 4;
        dst[0] = tf32r(v.x); dst[1] = tf32r(v.y); dst[2] = tf32r(v.z); dst[3] = tf32r(v.w);
    }
}

// ---------------------------------------------------------------------------
// K1: scores = relu(E @ W1s) @ W2s   -> g_scores [V,16]
// ---------------------------------------------------------------------------
__global__ __launch_bounds__(256, 1)
void scores_kernel(const float* __restrict__ E, const float* __restrict__ W1,
                   const float* __restrict__ W2) {
    float* Hs  = smem;                       // [128][132]
    float* Es  = Hs + TM * HS_LD;            // [128][36]
    float* Bs  = Es + TM * ES_LD;            // [32][132]
    float* W2s = Es;                         // reuse after phase A: [128][20]

    const int tid  = threadIdx.x;
    const int lane = tid & 31, w = tid >> 5;
    const int q = lane >> 2, t4 = lane & 3;
    const int node0 = blockIdx.x * TM;
    const int rowsValid = min(TM, VN - node0);

    // ---- phase A: h = relu(E_tile @ W1)  (warp tile 32x64) ----
    const int wm = w >> 1, wn = w & 1;
    float acc[2][8][4];
    #pragma unroll
    for (int mi = 0; mi < 2; mi++)
        #pragma unroll
        for (int ni = 0; ni < 8; ni++)
            #pragma unroll
            for (int j = 0; j < 4; j++) acc[mi][ni][j] = 0.f;

    for (int kc = 0; kc < VDN / KC; kc++) {
        load_E_chunk(Es, E, node0, rowsValid, kc, tid);
        load_W1_chunk(Bs, W1, kc, tid);
        __syncthreads();
        #pragma unroll
        for (int ks = 0; ks < 4; ks++) {
            const int kk = ks * 8;
            uint32_t afr[2][4];
            #pragma unroll
            for (int mi = 0; mi < 2; mi++) {
                int r0 = wm * 32 + mi * 16;
                afr[mi][0] = __float_as_uint(Es[(r0 + q) * ES_LD + kk + t4]);
                afr[mi][1] = __float_as_uint(Es[(r0 + q + 8) * ES_LD + kk + t4]);
                afr[mi][2] = __float_as_uint(Es[(r0 + q) * ES_LD + kk + t4 + 4]);
                afr[mi][3] = __float_as_uint(Es[(r0 + q + 8) * ES_LD + kk + t4 + 4]);
            }
            #pragma unroll
            for (int ni = 0; ni < 8; ni++) {
                int n0 = wn * 64 + ni * 8;
                uint32_t bfr[2];
                bfr[0] = __float_as_uint(Bs[(kk + t4) * BS_LD + n0 + q]);
                bfr[1] = __float_as_uint(Bs[(kk + t4 + 4) * BS_LD + n0 + q]);
                mma_tf32(acc[0][ni], afr[0], bfr);
                mma_tf32(acc[1][ni], afr[1], bfr);
            }
        }
        __syncthreads();
    }

    // relu + store h (tf32-rounded) to smem
    #pragma unroll
    for (int mi = 0; mi < 2; mi++) {
        int r0 = wm * 32 + mi * 16;
        #pragma unroll
        for (int ni = 0; ni < 8; ni++) {
            int n0 = wn * 64 + ni * 8;
            Hs[(r0 + q) * HS_LD + n0 + 2 * t4]         = tf32r(fmaxf(acc[mi][ni][0], 0.f));
            Hs[(r0 + q) * HS_LD + n0 + 2 * t4 + 1]     = tf32r(fmaxf(acc[mi][ni][1], 0.f));
            Hs[(r0 + q + 8) * HS_LD + n0 + 2 * t4]     = tf32r(fmaxf(acc[mi][ni][2], 0.f));
            Hs[(r0 + q + 8) * HS_LD + n0 + 2 * t4 + 1] = tf32r(fmaxf(acc[mi][ni][3], 0.f));
        }
    }
    // stage W2 [128][16] (float4)
    #pragma unroll
    for (int i = 0; i < 2; i++) {
        int idx = tid + i * 256;                // 512 float4
        int k = idx >> 2, n4 = idx & 3;
        float4 v = reinterpret_cast<const float4*>(W2)[(size_t)k * (NH / 4) + n4];
        float* dst = W2s + k * W2_LD + n4 * 4;
        dst[0] = tf32r(v.x); dst[1] = tf32r(v.y); dst[2] = tf32r(v.z); dst[3] = tf32r(v.w);
    }
    __syncthreads();

    // ---- phase C: scores = h @ W2  (warp w owns rows [16w,16w+16)) ----
    float sacc[2][4] = {};
    #pragma unroll
    for (int k0 = 0; k0 < HIDN; k0 += 8) {
        uint32_t afr[4];
        int r0 = w * 16;
        afr[0] = __float_as_uint(Hs[(r0 + q) * HS_LD + k0 + t4]);
        afr[1] = __float_as_uint(Hs[(r0 + q + 8) * HS_LD + k0 + t4]);
        afr[2] = __float_as_uint(Hs[(r0 + q) * HS_LD + k0 + t4 + 4]);
        afr[3] = __float_as_uint(Hs[(r0 + q + 8) * HS_LD + k0 + t4 + 4]);
        #pragma unroll
        for (int ni = 0; ni < 2; ni++) {
            uint32_t bfr[2];
            bfr[0] = __float_as_uint(W2s[(k0 + t4) * W2_LD + ni * 8 + q]);
            bfr[1] = __float_as_uint(W2s[(k0 + t4 + 4) * W2_LD + ni * 8 + q]);
            mma_tf32(sacc[ni], afr, bfr);
        }
    }
    #pragma unroll
    for (int ni = 0; ni < 2; ni++) {
        int col = ni * 8 + 2 * t4;
        int r   = w * 16 + q;
        if (r < rowsValid) {
            g_scores[(size_t)(node0 + r) * NH + col]     = sacc[ni][0];
            g_scores[(size_t)(node0 + r) * NH + col + 1] = sacc[ni][1];
        }
        if (r + 8 < rowsValid) {
            g_scores[(size_t)(node0 + r + 8) * NH + col]     = sacc[ni][2];
            g_scores[(size_t)(node0 + r + 8) * NH + col + 1] = sacc[ni][3];
        }
    }
}

// ---------------------------------------------------------------------------
// K2: per-graph softmax over g_scores (in-place -> weights). One warp/graph.
// ---------------------------------------------------------------------------
__global__ void softmax_kernel() {
    int gw   = (blockIdx.x * blockDim.x + threadIdx.x) >> 5;
    int lane = threadIdx.x & 31;
    if (gw >= GN) return;
    int s0 = g_gstart[gw], s1 = g_gstart[gw + 1];
    if (s0 >= s1) return;
    int head = lane & 15, half = lane >> 4;

    float m = -3.4e38f;
    for (int v = s0 + half; v < s1; v += 2)
        m = fmaxf(m, g_scores[(size_t)v * NH + head]);
    m = fmaxf(m, __shfl_xor_sync(0xffffffffu, m, 16));

    float sum = 0.f;
    for (int v = s0 + half; v < s1; v += 2)
        sum += __expf(g_scores[(size_t)v * NH + head] - m);
    sum += __shfl_xor_sync(0xffffffffu, sum, 16);
    float inv = 1.f / sum;

    for (int v = s0 + half; v < s1; v += 2) {
        size_t idx = (size_t)v * NH + head;
        g_scores[idx] = __expf(g_scores[idx] - m) * inv;
    }
}

// ---------------------------------------------------------------------------
// K3: R = relu(relu(E@W1t)@W2t); weighted segment-sum into out [G,256]
// ---------------------------------------------------------------------------
__device__ __forceinline__ void flushg(float* __restrict__ out, int g, int col,
                                       float a, int node0, int rowsValid) {
    int gs = g_gstart[g], ge = g_gstart[g + 1];
    float* p = out + (size_t)g * GDN + col;
    if (gs >= node0 && ge <= node0 + rowsValid) *p = a;   // graph fully inside tile
    else atomicAdd(p, a);                                  // tile-boundary graph
}

__global__ __launch_bounds__(256, 1)
void transform_kernel(const float* __restrict__ E, const float* __restrict__ W1,
                      const float* __restrict__ W2, const int* __restrict__ seg,
                      float* __restrict__ out) {
    float* Hs  = smem;                         // [128][132]: h, later R-chunk staging
    float* Es  = Hs + TM * HS_LD;              // phase A [128][36]
    float* Bs  = Es + TM * ES_LD;              // phase A [32][132]
    float* Wc  = Es;                           // phase C: W2t chunk [32][260] (8320 <= 8832)
    float* Wgt = Es + 8832;                    // weights [128][16]
    int*   SegS = (int*)(Wgt + TM * NH);       // [128]

    const int tid  = threadIdx.x;
    const int lane = tid & 31, w = tid >> 5;
    const int q = lane >> 2, t4 = lane & 3;
    const int node0 = blockIdx.x * TM;
    const int rowsValid = min(TM, VN - node0);

    // preload weights (float4) + segment ids (regions disjoint from phase A buffers)
    #pragma unroll
    for (int i = 0; i < 2; i++) {
        int idx = tid + i * 256;                // 512 float4 = [128][16]
        int r = idx >> 2, h4 = idx & 3;
        float4 v = make_float4(0.f, 0.f, 0.f, 0.f);
        if (r < rowsValid)
            v = reinterpret_cast<const float4*>(g_scores)[(size_t)(node0 + r) * (NH / 4) + h4];
        float* dst = Wgt + r * NH + h4 * 4;
        dst[0] = v.x; dst[1] = v.y; dst[2] = v.z; dst[3] = v.w;
    }
    if (tid < TM) SegS[tid] = (node0 + tid < VN) ? seg[node0 + tid] : -1;

    // ---- phase A: h = relu(E_tile @ W1t) ----
    const int wm = w >> 1, wn = w & 1;
    {
        float acc[2][8][4];
        #pragma unroll
        for (int mi = 0; mi < 2; mi++)
            #pragma unroll
            for (int ni = 0; ni < 8; ni++)
                #pragma unroll
                for (int j = 0; j < 4; j++) acc[mi][ni][j] = 0.f;

        for (int kc = 0; kc < VDN / KC; kc++) {
            load_E_chunk(Es, E, node0, rowsValid, kc, tid);
            load_W1_chunk(Bs, W1, kc, tid);
            __syncthreads();
            #pragma unroll
            for (int ks = 0; ks < 4; ks++) {
                const int kk = ks * 8;
                uint32_t afr[2][4];
                #pragma unroll
                for (int mi = 0; mi < 2; mi++) {
                    int r0 = wm * 32 + mi * 16;
                    afr[mi][0] = __float_as_uint(Es[(r0 + q) * ES_LD + kk + t4]);
                    afr[mi][1] = __float_as_uint(Es[(r0 + q + 8) * ES_LD + kk + t4]);
                    afr[mi][2] = __float_as_uint(Es[(r0 + q) * ES_LD + kk + t4 + 4]);
                    afr[mi][3] = __float_as_uint(Es[(r0 + q + 8) * ES_LD + kk + t4 + 4]);
                }
                #pragma unroll
                for (int ni = 0; ni < 8; ni++) {
                    int n0 = wn * 64 + ni * 8;
                    uint32_t bfr[2];
                    bfr[0] = __float_as_uint(Bs[(kk + t4) * BS_LD + n0 + q]);
                    bfr[1] = __float_as_uint(Bs[(kk + t4 + 4) * BS_LD + n0 + q]);
                    mma_tf32(acc[0][ni], afr[0], bfr);
                    mma_tf32(acc[1][ni], afr[1], bfr);
                }
            }
            __syncthreads();
        }
        #pragma unroll
        for (int mi = 0; mi < 2; mi++) {
            int r0 = wm * 32 + mi * 16;
            #pragma unroll
            for (int ni = 0; ni < 8; ni++) {
                int n0 = wn * 64 + ni * 8;
                Hs[(r0 + q) * HS_LD + n0 + 2 * t4]         = tf32r(fmaxf(acc[mi][ni][0], 0.f));
                Hs[(r0 + q) * HS_LD + n0 + 2 * t4 + 1]     = tf32r(fmaxf(acc[mi][ni][1], 0.f));
                Hs[(r0 + q + 8) * HS_LD + n0 + 2 * t4]     = tf32r(fmaxf(acc[mi][ni][2], 0.f));
                Hs[(r0 + q + 8) * HS_LD + n0 + 2 * t4 + 1] = tf32r(fmaxf(acc[mi][ni][3], 0.f));
            }
        }
    }

    // ---- phase C: R = h @ W2t  (M=128,N=256,K=128; warp tile 64x64) ----
    const int wm2 = w >> 2, wn2 = w & 3;
    float acc2[4][8][4];
    #pragma unroll
    for (int mi = 0; mi < 4; mi++)
        #pragma unroll
        for (int ni = 0; ni < 8; ni++)
            #pragma unroll
            for (int j = 0; j < 4; j++) acc2[mi][ni][j] = 0.f;

    for (int kc = 0; kc < 4; kc++) {
        __syncthreads();
        #pragma unroll
        for (int i = 0; i < 8; i++) {           // W2t chunk [32][256] = 2048 float4
            int idx = tid + i * 256;
            int k = idx >> 6, n4 = idx & 63;
            float4 v = reinterpret_cast<const float4*>(W2)[(size_t)(kc * 32 + k) * (GDN / 4) + n4];
            float* dst = Wc + k * WC_LD + n4 * 4;
            dst[0] = tf32r(v.x); dst[1] = tf32r(v.y); dst[2] = tf32r(v.z); dst[3] = tf32r(v.w);
        }
        __syncthreads();
        #pragma unroll
        for (int ks = 0; ks < 4; ks++) {
            const int kkl = ks * 8;            // k within chunk
            const int kkg = kc * 32 + kkl;     // global k (Hs column)
            uint32_t afr[4][4];
            #pragma unroll
            for (int mi = 0; mi < 4; mi++) {
                int r0 = wm2 * 64 + mi * 16;
                afr[mi][0] = __float_as_uint(Hs[(r0 + q) * HS_LD + kkg + t4]);
                afr[mi][1] = __float_as_uint(Hs[(r0 + q + 8) * HS_LD + kkg + t4]);
                afr[mi][2] = __float_as_uint(Hs[(r0 + q) * HS_LD + kkg + t4 + 4]);
                afr[mi][3] = __float_as_uint(Hs[(r0 + q + 8) * HS_LD + kkg + t4 + 4]);
            }
            #pragma unroll
            for (int ni = 0; ni < 8; ni++) {
                int n0 = wn2 * 64 + ni * 8;
                uint32_t bfr[2];
                bfr[0] = __float_as_uint(Wc[(kkl + t4) * WC_LD + n0 + q]);
                bfr[1] = __float_as_uint(Wc[(kkl + t4 + 4) * WC_LD + n0 + q]);
                #pragma unroll
                for (int mi = 0; mi < 4; mi++)
                    mma_tf32(acc2[mi][ni], afr[mi], bfr);
            }
        }
    }

    // ---- epilogue: relu * weight, stage 128-col chunk, sorted-segment reduce ----
    for (int ch = 0; ch < 2; ch++) {
        __syncthreads();
        if ((wn2 >> 1) == ch) {
            #pragma unroll
            for (int mi = 0; mi < 4; mi++) {
                int r0 = wm2 * 64 + mi * 16;
                #pragma unroll
                for (int ni = 0; ni < 8; ni++) {
                    int n0 = wn2 * 64 + ni * 8;    // absolute col base (8-aligned => one head)
                    int head = n0 >> 4;
                    int cb = n0 - ch * 128 + 2 * t4;
                    float w0 = Wgt[(r0 + q) * NH + head];
                    float w2v = Wgt[(r0 + q + 8) * NH + head];
                    Hs[(r0 + q) * HS_LD + cb]         = fmaxf(acc2[mi][ni][0], 0.f) * w0;
                    Hs[(r0 + q) * HS_LD + cb + 1]     = fmaxf(acc2[mi][ni][1], 0.f) * w0;
                    Hs[(r0 + q + 8) * HS_LD + cb]     = fmaxf(acc2[mi][ni][2], 0.f) * w2v;
                    Hs[(r0 + q + 8) * HS_LD + cb + 1] = fmaxf(acc2[mi][ni][3], 0.f) * w2v;
                }
            }
        }
        __syncthreads();
        if (tid < 128) {
            int col = ch * 128 + tid;
            int g = SegS[0];
            float a = 0.f;
            for (int r = 0; r < rowsValid; r++) {
                int gr = SegS[r];
                if (gr != g) {
                    flushg(out, g, col, a, node0, rowsValid);
                    g = gr; a = 0.f;
                }
                a += Hs[r * HS_LD + tid];
            }
            flushg(out, g, col, a, node0, rowsValid);
        }
    }
}

// ---------------------------------------------------------------------------
// launch
// ---------------------------------------------------------------------------
extern "C" void kernel_launch(void* const* d_in, const int* in_sizes, int n_in,
                              void* d_out, int out_size) {
    const float* E   = (const float*)d_in[0];
    const int*   seg = (const int*)d_in[1];
    int idx = (n_in > 2 && in_sizes[2] == VDN * HIDN) ? 2 : 3;  // skip num_graphs scalar if present
    const float* sw1 = (const float*)d_in[idx];
    const float* sw2 = (const float*)d_in[idx + 1];
    const float* tw1 = (const float*)d_in[idx + 2];
    const float* tw2 = (const float*)d_in[idx + 3];
    float* out = (float*)d_out;

    const int SMEM_K1 = (TM * HS_LD + TM * ES_LD + KC * BS_LD) * 4;                 // 102912
    const int SMEM_K3 = (TM * HS_LD + 8832 + TM * NH) * 4 + TM * 4;                 // 111616

    cudaFuncSetAttribute(scores_kernel, cudaFuncAttributeMaxDynamicSharedMemorySize, SMEM_K1);
    cudaFuncSetAttribute(transform_kernel, cudaFuncAttributeMaxDynamicSharedMemorySize, SMEM_K3);

    zero_kernel<<<1024, 256>>>((float4*)out, out_size / 4);
    gstart_kernel<<<(VN + 255) / 256, 256>>>(seg);
    scores_kernel<<<(VN + TM - 1) / TM, 256, SMEM_K1>>>(E, sw1, sw2);
    softmax_kernel<<<(GN * 32 + 255) / 256, 256>>>();
    transform_kernel<<<(VN + TM - 1) / TM, 256, SMEM_K3>>>(E, tw1, tw2, seg, out);
}

// round 4
// speedup vs baseline: 1.2094x; 1.2094x over previous
#include <cuda_runtime.h>
#include <cstdint>

// Problem shapes (fixed for this dataset)
#define VN     1000000
#define VN_PAD 1000064   // 7813 * 128
#define VDN    256
#define HIDN   128
#define NH     16
#define GDN    256
#define GN     50000

#define TM   128      // nodes per tile
#define KC   32       // K-chunk for GEMM1
#define ES_LD 36      // 32 + 4 pad
#define BS_LD 132     // 128 + 4 pad
#define HS_LD 132
#define W2_LD 20
#define WC_LD 260     // 256 + 4 pad
#define NT   512      // threads per CTA (16 warps)

// Scratch (device globals: no allocations allowed)
__device__ float g_scores[(size_t)VN * NH];        // scores, then softmax weights (in-place)
__device__ float g_ht[(size_t)VN_PAD * HIDN];      // h_t = relu(E @ W1t), tf32-rounded
__device__ int   g_gstart[GN + 1];                 // gstart[g] = first node with seg >= g

extern __shared__ float smem[];

// ---------------------------------------------------------------------------
// helpers
// ---------------------------------------------------------------------------
__device__ __forceinline__ float tf32r(float x) {
    uint32_t r;
    asm("cvt.rna.tf32.f32 %0, %1;" : "=r"(r) : "f"(x));
    return __uint_as_float(r);
}

__device__ __forceinline__ void mma_tf32(float c[4], const uint32_t a[4], const uint32_t b[2]) {
    asm volatile(
        "mma.sync.aligned.m16n8k8.row.col.f32.tf32.tf32.f32 "
        "{%0,%1,%2,%3}, {%4,%5,%6,%7}, {%8,%9}, {%0,%1,%2,%3};\n"
        : "+f"(c[0]), "+f"(c[1]), "+f"(c[2]), "+f"(c[3])
        : "r"(a[0]), "r"(a[1]), "r"(a[2]), "r"(a[3]), "r"(b[0]), "r"(b[1]));
}

__device__ __forceinline__ void sts_tf32_f4(float* dst, float4 v) {
    dst[0] = tf32r(v.x); dst[1] = tf32r(v.y); dst[2] = tf32r(v.z); dst[3] = tf32r(v.w);
}

// ---------------------------------------------------------------------------
// K0a: zero output (float4, wide grid)
// ---------------------------------------------------------------------------
__global__ void zero_kernel(float4* __restrict__ out, int n4) {
    const float4 z = make_float4(0.f, 0.f, 0.f, 0.f);
    for (int i = blockIdx.x * blockDim.x + threadIdx.x; i < n4; i += gridDim.x * blockDim.x)
        out[i] = z;
}

// ---------------------------------------------------------------------------
// K0b: segment offsets (seg sorted ascending)
// ---------------------------------------------------------------------------
__global__ void gstart_kernel(const int* __restrict__ seg) {
    int v = blockIdx.x * blockDim.x + threadIdx.x;
    if (v >= VN) return;
    int s  = seg[v];
    int sp = (v == 0) ? -1 : seg[v - 1];
    for (int g = sp + 1; g <= s; g++) g_gstart[g] = v;
    if (v == VN - 1)
        for (int g = s + 1; g <= GN; g++) g_gstart[g] = VN;
}

// ---------------------------------------------------------------------------
// K1 (fused): h_s = relu(E@W1s); h_t = relu(E@W1t) -> g_ht;
//             scores = h_s @ W2s -> g_scores.   E read ONCE.
// 512 threads: phase-A warp grid 4x4, each warp 32x32 per GEMM.
// ---------------------------------------------------------------------------
__global__ __launch_bounds__(NT, 1)
void fused_k1(const float* __restrict__ E, const float* __restrict__ W1s,
              const float* __restrict__ W2s_g, const float* __restrict__ W1t) {
    float* Hs  = smem;                        // [128][132]
    float* Es  = Hs + TM * HS_LD;             // [128][36]
    float* BsS = Es + TM * ES_LD;             // [32][132]
    float* BsT = BsS + KC * BS_LD;            // [32][132]
    float* W2s = Es;                          // alias after phase A: [128][20]

    const int tid  = threadIdx.x;
    const int lane = tid & 31, w = tid >> 5;
    const int q = lane >> 2, t4 = lane & 3;
    const int node0 = blockIdx.x * TM;
    const int rowsValid = min(TM, VN - node0);

    const int wm = w >> 2, wn = w & 3;        // 4x4 warp grid

    // per-thread load coordinates (2 float4 each per chunk)
    const int eR0 = tid >> 3,           eC0 = tid & 7;
    const int eR1 = (tid + NT) >> 3,    eC1 = (tid + NT) & 7;
    const int wK0 = tid >> 5,           wN0 = tid & 31;
    const int wK1 = (tid + NT) >> 5,    wN1 = (tid + NT) & 31;

    float4 pe0, pe1, ps0, ps1, pt0, pt1;
    const float4 zf4 = make_float4(0.f, 0.f, 0.f, 0.f);

    // prefetch chunk 0
    {
        pe0 = (eR0 < rowsValid) ? reinterpret_cast<const float4*>(E)[(size_t)(node0 + eR0) * 64 + eC0] : zf4;
        pe1 = (eR1 < rowsValid) ? reinterpret_cast<const float4*>(E)[(size_t)(node0 + eR1) * 64 + eC1] : zf4;
        ps0 = reinterpret_cast<const float4*>(W1s)[(size_t)wK0 * 32 + wN0];
        ps1 = reinterpret_cast<const float4*>(W1s)[(size_t)wK1 * 32 + wN1];
        pt0 = reinterpret_cast<const float4*>(W1t)[(size_t)wK0 * 32 + wN0];
        pt1 = reinterpret_cast<const float4*>(W1t)[(size_t)wK1 * 32 + wN1];
    }

    float accS[2][4][4], accT[2][4][4];
    #pragma unroll
    for (int mi = 0; mi < 2; mi++)
        #pragma unroll
        for (int ni = 0; ni < 4; ni++)
            #pragma unroll
            for (int j = 0; j < 4; j++) { accS[mi][ni][j] = 0.f; accT[mi][ni][j] = 0.f; }

    for (int kc = 0; kc < VDN / KC; kc++) {
        // commit prefetched regs -> smem (tf32)
        sts_tf32_f4(Es + eR0 * ES_LD + eC0 * 4, pe0);
        sts_tf32_f4(Es + eR1 * ES_LD + eC1 * 4, pe1);
        sts_tf32_f4(BsS + wK0 * BS_LD + wN0 * 4, ps0);
        sts_tf32_f4(BsS + wK1 * BS_LD + wN1 * 4, ps1);
        sts_tf32_f4(BsT + wK0 * BS_LD + wN0 * 4, pt0);
        sts_tf32_f4(BsT + wK1 * BS_LD + wN1 * 4, pt1);
        __syncthreads();

        if (kc < VDN / KC - 1) {   // prefetch next chunk (overlaps MMA below)
            int kn = kc + 1;
            pe0 = (eR0 < rowsValid) ? reinterpret_cast<const float4*>(E)[(size_t)(node0 + eR0) * 64 + kn * 8 + eC0] : zf4;
            pe1 = (eR1 < rowsValid) ? reinterpret_cast<const float4*>(E)[(size_t)(node0 + eR1) * 64 + kn * 8 + eC1] : zf4;
            ps0 = reinterpret_cast<const float4*>(W1s)[(size_t)(kn * KC + wK0) * 32 + wN0];
            ps1 = reinterpret_cast<const float4*>(W1s)[(size_t)(kn * KC + wK1) * 32 + wN1];
            pt0 = reinterpret_cast<const float4*>(W1t)[(size_t)(kn * KC + wK0) * 32 + wN0];
            pt1 = reinterpret_cast<const float4*>(W1t)[(size_t)(kn * KC + wK1) * 32 + wN1];
        }

        #pragma unroll
        for (int ks = 0; ks < 4; ks++) {
            const int kk = ks * 8;
            uint32_t afr[2][4];
            #pragma unroll
            for (int mi = 0; mi < 2; mi++) {
                int r0 = wm * 32 + mi * 16;
                afr[mi][0] = __float_as_uint(Es[(r0 + q) * ES_LD + kk + t4]);
                afr[mi][1] = __float_as_uint(Es[(r0 + q + 8) * ES_LD + kk + t4]);
                afr[mi][2] = __float_as_uint(Es[(r0 + q) * ES_LD + kk + t4 + 4]);
                afr[mi][3] = __float_as_uint(Es[(r0 + q + 8) * ES_LD + kk + t4 + 4]);
            }
            #pragma unroll
            for (int ni = 0; ni < 4; ni++) {
                int n0 = wn * 32 + ni * 8;
                uint32_t bS[2], bT[2];
                bS[0] = __float_as_uint(BsS[(kk + t4) * BS_LD + n0 + q]);
                bS[1] = __float_as_uint(BsS[(kk + t4 + 4) * BS_LD + n0 + q]);
                bT[0] = __float_as_uint(BsT[(kk + t4) * BS_LD + n0 + q]);
                bT[1] = __float_as_uint(BsT[(kk + t4 + 4) * BS_LD + n0 + q]);
                mma_tf32(accS[0][ni], afr[0], bS);
                mma_tf32(accS[1][ni], afr[1], bS);
                mma_tf32(accT[0][ni], afr[0], bT);
                mma_tf32(accT[1][ni], afr[1], bT);
            }
        }
        __syncthreads();
    }

    // ---- h_s -> Hs (relu + tf32), stage W2s ----
    #pragma unroll
    for (int mi = 0; mi < 2; mi++) {
        int r0 = wm * 32 + mi * 16;
        #pragma unroll
        for (int ni = 0; ni < 4; ni++) {
            int n0 = wn * 32 + ni * 8;
            Hs[(r0 + q) * HS_LD + n0 + 2 * t4]         = tf32r(fmaxf(accS[mi][ni][0], 0.f));
            Hs[(r0 + q) * HS_LD + n0 + 2 * t4 + 1]     = tf32r(fmaxf(accS[mi][ni][1], 0.f));
            Hs[(r0 + q + 8) * HS_LD + n0 + 2 * t4]     = tf32r(fmaxf(accS[mi][ni][2], 0.f));
            Hs[(r0 + q + 8) * HS_LD + n0 + 2 * t4 + 1] = tf32r(fmaxf(accS[mi][ni][3], 0.f));
        }
    }
    {   // W2s [128][16] = 512 float4, 1/thread
        int k = tid >> 2, n4 = tid & 3;
        float4 v = reinterpret_cast<const float4*>(W2s_g)[(size_t)k * (NH / 4) + n4];
        sts_tf32_f4(W2s + k * W2_LD + n4 * 4, v);
    }
    __syncthreads();

    // ---- scores = h_s @ W2s (warps 0..7, rows 16w..16w+16) ----
    if (w < 8) {
        float sacc[2][4] = {};
        #pragma unroll
        for (int k0 = 0; k0 < HIDN; k0 += 8) {
            uint32_t afr[4];
            int r0 = w * 16;
            afr[0] = __float_as_uint(Hs[(r0 + q) * HS_LD + k0 + t4]);
            afr[1] = __float_as_uint(Hs[(r0 + q + 8) * HS_LD + k0 + t4]);
            afr[2] = __float_as_uint(Hs[(r0 + q) * HS_LD + k0 + t4 + 4]);
            afr[3] = __float_as_uint(Hs[(r0 + q + 8) * HS_LD + k0 + t4 + 4]);
            #pragma unroll
            for (int ni = 0; ni < 2; ni++) {
                uint32_t bfr[2];
                bfr[0] = __float_as_uint(W2s[(k0 + t4) * W2_LD + ni * 8 + q]);
                bfr[1] = __float_as_uint(W2s[(k0 + t4 + 4) * W2_LD + ni * 8 + q]);
                mma_tf32(sacc[ni], afr, bfr);
            }
        }
        #pragma unroll
        for (int ni = 0; ni < 2; ni++) {
            int col = ni * 8 + 2 * t4;
            int r   = w * 16 + q;
            if (r < rowsValid) {
                g_scores[(size_t)(node0 + r) * NH + col]     = sacc[ni][0];
                g_scores[(size_t)(node0 + r) * NH + col + 1] = sacc[ni][1];
            }
            if (r + 8 < rowsValid) {
                g_scores[(size_t)(node0 + r + 8) * NH + col]     = sacc[ni][2];
                g_scores[(size_t)(node0 + r + 8) * NH + col + 1] = sacc[ni][3];
            }
        }
    }
    __syncthreads();

    // ---- h_t -> Hs (relu + tf32), then coalesced write to g_ht ----
    #pragma unroll
    for (int mi = 0; mi < 2; mi++) {
        int r0 = wm * 32 + mi * 16;
        #pragma unroll
        for (int ni = 0; ni < 4; ni++) {
            int n0 = wn * 32 + ni * 8;
            Hs[(r0 + q) * HS_LD + n0 + 2 * t4]         = tf32r(fmaxf(accT[mi][ni][0], 0.f));
            Hs[(r0 + q) * HS_LD + n0 + 2 * t4 + 1]     = tf32r(fmaxf(accT[mi][ni][1], 0.f));
            Hs[(r0 + q + 8) * HS_LD + n0 + 2 * t4]     = tf32r(fmaxf(accT[mi][ni][2], 0.f));
            Hs[(r0 + q + 8) * HS_LD + n0 + 2 * t4 + 1] = tf32r(fmaxf(accT[mi][ni][3], 0.f));
        }
    }
    __syncthreads();
    #pragma unroll
    for (int i = 0; i < 8; i++) {              // 4096 float4
        int idx = tid + i * NT;
        int r = idx >> 5, c4 = idx & 31;
        const float* s = Hs + r * HS_LD + c4 * 4;
        float4 v = make_float4(s[0], s[1], s[2], s[3]);
        reinterpret_cast<float4*>(g_ht)[(size_t)(node0 + r) * (HIDN / 4) + c4] = v;
    }
}

// ---------------------------------------------------------------------------
// K2: per-graph softmax over g_scores (in-place -> weights). One warp/graph.
// ---------------------------------------------------------------------------
__global__ void softmax_kernel() {
    int gw   = (blockIdx.x * blockDim.x + threadIdx.x) >> 5;
    int lane = threadIdx.x & 31;
    if (gw >= GN) return;
    int s0 = g_gstart[gw], s1 = g_gstart[gw + 1];
    if (s0 >= s1) return;
    int head = lane & 15, half = lane >> 4;

    float m = -3.4e38f;
    for (int v = s0 + half; v < s1; v += 2)
        m = fmaxf(m, g_scores[(size_t)v * NH + head]);
    m = fmaxf(m, __shfl_xor_sync(0xffffffffu, m, 16));

    float sum = 0.f;
    for (int v = s0 + half; v < s1; v += 2)
        sum += __expf(g_scores[(size_t)v * NH + head] - m);
    sum += __shfl_xor_sync(0xffffffffu, sum, 16);
    float inv = 1.f / sum;

    for (int v = s0 + half; v < s1; v += 2) {
        size_t idx = (size_t)v * NH + head;
        g_scores[idx] = __expf(g_scores[idx] - m) * inv;
    }
}

// ---------------------------------------------------------------------------
// K3: R = relu(h_t @ W2t) * weights; sorted-segment sum into out [G,256]
// ---------------------------------------------------------------------------
__device__ __forceinline__ void flushg(float* __restrict__ out, int g, int col,
                                       float a, int node0, int rowsValid) {
    int gs = g_gstart[g], ge = g_gstart[g + 1];
    float* p = out + (size_t)g * GDN + col;
    if (gs >= node0 && ge <= node0 + rowsValid) *p = a;   // graph fully inside tile
    else atomicAdd(p, a);                                  // tile-boundary graph
}

__global__ __launch_bounds__(NT, 1)
void transform_kernel(const float* __restrict__ W2, const int* __restrict__ seg,
                      float* __restrict__ out) {
    float* Hs  = smem;                         // [128][132]: h_t tile, later staging
    float* Wc  = Hs + TM * HS_LD;              // [32][260]
    float* Wgt = Wc + KC * WC_LD;              // [128][16]
    int*   SegS = (int*)(Wgt + TM * NH);       // [128]

    const int tid  = threadIdx.x;
    const int lane = tid & 31, w = tid >> 5;
    const int q = lane >> 2, t4 = lane & 3;
    const int node0 = blockIdx.x * TM;
    const int rowsValid = min(TM, VN - node0);

    // weights + seg ids
    {
        int r = tid >> 2, h4 = tid & 3;
        float4 v = make_float4(0.f, 0.f, 0.f, 0.f);
        if (r < rowsValid)
            v = reinterpret_cast<const float4*>(g_scores)[(size_t)(node0 + r) * (NH / 4) + h4];
        float* dst = Wgt + r * NH + h4 * 4;
        dst[0] = v.x; dst[1] = v.y; dst[2] = v.z; dst[3] = v.w;
    }
    if (tid < TM) SegS[tid] = (node0 + tid < VN) ? seg[node0 + tid] : -1;

    // h_t tile -> smem (already tf32-rounded)
    #pragma unroll
    for (int i = 0; i < 8; i++) {              // 4096 float4
        int idx = tid + i * NT;
        int r = idx >> 5, c4 = idx & 31;
        float4 v = reinterpret_cast<const float4*>(g_ht)[(size_t)(node0 + r) * (HIDN / 4) + c4];
        float* dst = Hs + r * HS_LD + c4 * 4;
        dst[0] = v.x; dst[1] = v.y; dst[2] = v.z; dst[3] = v.w;
    }

    // prefetch W2t chunk 0 (2048 f4 / 512 thr = 4/thread)
    const int cK0 = tid >> 6,            cN0 = tid & 63;
    const int cK1 = (tid + NT) >> 6,     cN1 = (tid + NT) & 63;
    const int cK2 = (tid + 2*NT) >> 6,   cN2 = (tid + 2*NT) & 63;
    const int cK3 = (tid + 3*NT) >> 6,   cN3 = (tid + 3*NT) & 63;
    float4 pw0 = reinterpret_cast<const float4*>(W2)[(size_t)cK0 * 64 + cN0];
    float4 pw1 = reinterpret_cast<const float4*>(W2)[(size_t)cK1 * 64 + cN1];
    float4 pw2 = reinterpret_cast<const float4*>(W2)[(size_t)cK2 * 64 + cN2];
    float4 pw3 = reinterpret_cast<const float4*>(W2)[(size_t)cK3 * 64 + cN3];

    // ---- GEMM2: R = h_t @ W2t  (M=128,N=256,K=128), warp grid 4x4, tile 32x64
    const int wm2 = w >> 2, wn2 = w & 3;
    float acc2[2][8][4];
    #pragma unroll
    for (int mi = 0; mi < 2; mi++)
        #pragma unroll
        for (int ni = 0; ni < 8; ni++)
            #pragma unroll
            for (int j = 0; j < 4; j++) acc2[mi][ni][j] = 0.f;

    for (int kc = 0; kc < 4; kc++) {
        sts_tf32_f4(Wc + cK0 * WC_LD + cN0 * 4, pw0);
        sts_tf32_f4(Wc + cK1 * WC_LD + cN1 * 4, pw1);
        sts_tf32_f4(Wc + cK2 * WC_LD + cN2 * 4, pw2);
        sts_tf32_f4(Wc + cK3 * WC_LD + cN3 * 4, pw3);
        __syncthreads();
        if (kc < 3) {
            int kn = kc + 1;
            pw0 = reinterpret_cast<const float4*>(W2)[(size_t)(kn * KC + cK0) * 64 + cN0];
            pw1 = reinterpret_cast<const float4*>(W2)[(size_t)(kn * KC + cK1) * 64 + cN1];
            pw2 = reinterpret_cast<const float4*>(W2)[(size_t)(kn * KC + cK2) * 64 + cN2];
            pw3 = reinterpret_cast<const float4*>(W2)[(size_t)(kn * KC + cK3) * 64 + cN3];
        }
        #pragma unroll
        for (int ks = 0; ks < 4; ks++) {
            const int kkl = ks * 8;
            const int kkg = kc * KC + kkl;
            uint32_t afr[2][4];
            #pragma unroll
            for (int mi = 0; mi < 2; mi++) {
                int r0 = wm2 * 32 + mi * 16;
                afr[mi][0] = __float_as_uint(Hs[(r0 + q) * HS_LD + kkg + t4]);
                afr[mi][1] = __float_as_uint(Hs[(r0 + q + 8) * HS_LD + kkg + t4]);
                afr[mi][2] = __float_as_uint(Hs[(r0 + q) * HS_LD + kkg + t4 + 4]);
                afr[mi][3] = __float_as_uint(Hs[(r0 + q + 8) * HS_LD + kkg + t4 + 4]);
            }
            #pragma unroll
            for (int ni = 0; ni < 8; ni++) {
                int n0 = wn2 * 64 + ni * 8;
                uint32_t bfr[2];
                bfr[0] = __float_as_uint(Wc[(kkl + t4) * WC_LD + n0 + q]);
                bfr[1] = __float_as_uint(Wc[(kkl + t4 + 4) * WC_LD + n0 + q]);
                mma_tf32(acc2[0][ni], afr[0], bfr);
                mma_tf32(acc2[1][ni], afr[1], bfr);
            }
        }
        __syncthreads();
    }

    // ---- epilogue: relu * weight, stage 128-col chunk, sorted-segment reduce
    for (int ch = 0; ch < 2; ch++) {
        __syncthreads();
        if ((wn2 >> 1) == ch) {
            #pragma unroll
            for (int mi = 0; mi < 2; mi++) {
                int r0 = wm2 * 32 + mi * 16;
                #pragma unroll
                for (int ni = 0; ni < 8; ni++) {
                    int n0 = wn2 * 64 + ni * 8;    // 8-aligned => single head
                    int head = n0 >> 4;
                    int cb = n0 - ch * 128 + 2 * t4;
                    float w0  = Wgt[(r0 + q) * NH + head];
                    float w2v = Wgt[(r0 + q + 8) * NH + head];
                    Hs[(r0 + q) * HS_LD + cb]         = fmaxf(acc2[mi][ni][0], 0.f) * w0;
                    Hs[(r0 + q) * HS_LD + cb + 1]     = fmaxf(acc2[mi][ni][1], 0.f) * w0;
                    Hs[(r0 + q + 8) * HS_LD + cb]     = fmaxf(acc2[mi][ni][2], 0.f) * w2v;
                    Hs[(r0 + q + 8) * HS_LD + cb + 1] = fmaxf(acc2[mi][ni][3], 0.f) * w2v;
                }
            }
        }
        __syncthreads();
        if (tid < 128) {
            int col = ch * 128 + tid;
            int g = SegS[0];
            float a = 0.f;
            for (int r = 0; r < rowsValid; r++) {
                int gr = SegS[r];
                if (gr != g) {
                    flushg(out, g, col, a, node0, rowsValid);
                    g = gr; a = 0.f;
                }
                a += Hs[r * HS_LD + tid];
            }
            flushg(out, g, col, a, node0, rowsValid);
        }
    }
}

// ---------------------------------------------------------------------------
// launch
// ---------------------------------------------------------------------------
extern "C" void kernel_launch(void* const* d_in, const int* in_sizes, int n_in,
                              void* d_out, int out_size) {
    const float* E   = (const float*)d_in[0];
    const int*   seg = (const int*)d_in[1];
    int idx = (n_in > 2 && in_sizes[2] == VDN * HIDN) ? 2 : 3;  // skip num_graphs scalar
    const float* sw1 = (const float*)d_in[idx];
    const float* sw2 = (const float*)d_in[idx + 1];
    const float* tw1 = (const float*)d_in[idx + 2];
    const float* tw2 = (const float*)d_in[idx + 3];
    float* out = (float*)d_out;

    const int SMEM_K1 = (TM * HS_LD + TM * ES_LD + 2 * KC * BS_LD) * 4;          // 119808
    const int SMEM_K3 = (TM * HS_LD + KC * WC_LD + TM * NH) * 4 + TM * 4;        // 109568

    cudaFuncSetAttribute(fused_k1, cudaFuncAttributeMaxDynamicSharedMemorySize, SMEM_K1);
    cudaFuncSetAttribute(transform_kernel, cudaFuncAttributeMaxDynamicSharedMemorySize, SMEM_K3);

    const int NTILES = (VN + TM - 1) / TM;   // 7813

    zero_kernel<<<1024, 256>>>((float4*)out, out_size / 4);
    gstart_kernel<<<(VN + 255) / 256, 256>>>(seg);
    fused_k1<<<NTILES, NT, SMEM_K1>>>(E, sw1, sw2, tw1);
    softmax_kernel<<<(GN * 32 + 255) / 256, 256>>>();
    transform_kernel<<<NTILES, NT, SMEM_K3>>>(tw2, seg, out);
}